// round 1
// baseline (speedup 1.0000x reference)
#include <cuda_runtime.h>
#include <cuda_bf16.h>
#include <cstdint>
#include <math.h>

// Problem constants
#define B_  1
#define S_  2048
#define H_  2048
#define NH_ 8
#define DH_ 256
#define SCALE_ 0.0625f   // 256^-0.5

// ---------------- scratch (device globals; no allocation allowed) -------------
__device__ float g_Q [S_ * (NH_ * DH_)];   // 2048 x 2048
__device__ float g_K [S_ * DH_];           // 2048 x 256
__device__ float g_KT[DH_ * S_];           // 256  x 2048
__device__ float g_V [S_ * DH_];           // 2048 x 256
__device__ float g_ctx[S_ * (NH_ * DH_)];  // 2048 x 2048

// ---------------- generic strided batched fp32 GEMM ---------------------------
// C[b] = A[b] (MxK, lda) * B[b] (KxN, ldb) -> C (MxN, ldc)
// BM=BN=64, BK=16, 16x16 threads, 4x4 microtile per thread.
#define BM 64
#define BN 64
#define BK 16

__global__ void gemm_kernel(const float* __restrict__ A,
                            const float* __restrict__ B,
                            float* __restrict__ C,
                            int M, int N, int K,
                            int lda, int ldb, int ldc,
                            long long aStride, long long bStride, long long cStride)
{
    const int batch = blockIdx.z;
    A += (long long)batch * aStride;
    B += (long long)batch * bStride;
    C += (long long)batch * cStride;

    __shared__ float As[BM][BK + 1];
    __shared__ float Bs[BK][BN + 1];

    const int tid = threadIdx.x;        // 0..255
    const int tx  = tid & 15;
    const int ty  = tid >> 4;
    const int rowBase = blockIdx.y * BM;
    const int colBase = blockIdx.x * BN;

    float acc[4][4] = {};

    // load-index precompute
    const int aIdx = tid * 4;           // 0..1023
    const int am   = aIdx / BK;         // 0..63
    const int ak   = aIdx % BK;         // 0,4,8,12
    const int bIdx = tid * 4;
    const int bk   = bIdx / BN;         // 0..15
    const int bn   = bIdx % BN;         // 0..60

    for (int kt = 0; kt < K; kt += BK) {
        const float* Ap = A + (long long)(rowBase + am) * lda + (kt + ak);
        #pragma unroll
        for (int u = 0; u < 4; u++) As[am][ak + u] = Ap[u];

        const float* Bp = B + (long long)(kt + bk) * ldb + (colBase + bn);
        #pragma unroll
        for (int u = 0; u < 4; u++) Bs[bk][bn + u] = Bp[u];

        __syncthreads();

        #pragma unroll
        for (int kk = 0; kk < BK; kk++) {
            float a[4], b[4];
            #pragma unroll
            for (int i = 0; i < 4; i++) a[i] = As[ty * 4 + i][kk];
            #pragma unroll
            for (int j = 0; j < 4; j++) b[j] = Bs[kk][tx * 4 + j];
            #pragma unroll
            for (int i = 0; i < 4; i++)
                #pragma unroll
                for (int j = 0; j < 4; j++)
                    acc[i][j] = fmaf(a[i], b[j], acc[i][j]);
        }
        __syncthreads();
    }

    #pragma unroll
    for (int i = 0; i < 4; i++) {
        float* Cp = C + (long long)(rowBase + ty * 4 + i) * ldc + colBase + tx * 4;
        #pragma unroll
        for (int j = 0; j < 4; j++) Cp[j] = acc[i][j];
    }
}

// ---------------- RoPE --------------------------------------------------------
// layout: buf[s*rowStride + h*DH + d], pairs (d, d+128), d in [0,128)
__global__ void rope_kernel(float* __restrict__ buf, const int* __restrict__ pos,
                            int nHeads, int rowStride)
{
    long long idx = (long long)blockIdx.x * blockDim.x + threadIdx.x;
    const long long total = (long long)S_ * nHeads * (DH_ / 2);
    if (idx >= total) return;
    int d = (int)(idx % (DH_ / 2));
    int h = (int)((idx / (DH_ / 2)) % nHeads);
    int s = (int)(idx / ((long long)(DH_ / 2) * nHeads));

    float p = (float)pos[s];
    // inv_freq[d] = 10000^(-2d/256)
    float inv = exp2f(-((float)(2 * d) / (float)DH_) * log2f(10000.0f));
    float ang = p * inv;
    float sn, cs;
    sincosf(ang, &sn, &cs);

    float* base = buf + (long long)s * rowStride + h * DH_;
    float a = base[d];
    float b = base[d + 128];
    base[d]       = a * cs - b * sn;
    base[d + 128] = b * cs + a * sn;
}

// ---------------- transpose (K: SxDH -> KT: DHxS) ------------------------------
__global__ void transpose_kernel(const float* __restrict__ in, float* __restrict__ out,
                                 int R, int C)
{
    __shared__ float tile[32][33];
    int c0 = blockIdx.x * 32;
    int r0 = blockIdx.y * 32;
    int tx = threadIdx.x, ty = threadIdx.y;   // 32 x 8
    #pragma unroll
    for (int i = 0; i < 32; i += 8)
        tile[ty + i][tx] = in[(long long)(r0 + ty + i) * C + (c0 + tx)];
    __syncthreads();
    #pragma unroll
    for (int i = 0; i < 32; i += 8)
        out[(long long)(c0 + ty + i) * R + (r0 + tx)] = tile[tx][ty + i];
}

// ---------------- scale + mask + softmax (in place on attn) --------------------
// grid: (S_, NH_), block: 256 threads, 8 cols per thread
__global__ void softmax_kernel(float* __restrict__ attn, const float* __restrict__ mask)
{
    const int i = blockIdx.x;
    const int h = blockIdx.y;
    float* row = attn + ((long long)h * S_ + i) * S_;
    const float* mrow = mask + (long long)i * S_;
    const int t = threadIdx.x;

    float vals[8];
    float mx = -INFINITY;
    #pragma unroll
    for (int j = 0; j < 8; j++) {
        int col = t + j * 256;
        float v = row[col] * SCALE_ + mrow[col];
        vals[j] = v;
        mx = fmaxf(mx, v);
    }

    __shared__ float red[256];
    red[t] = mx;
    __syncthreads();
    #pragma unroll
    for (int s = 128; s > 0; s >>= 1) {
        if (t < s) red[t] = fmaxf(red[t], red[t + s]);
        __syncthreads();
    }
    mx = red[0];
    __syncthreads();

    float sum = 0.0f;
    #pragma unroll
    for (int j = 0; j < 8; j++) {
        vals[j] = __expf(vals[j] - mx);
        sum += vals[j];
    }
    red[t] = sum;
    __syncthreads();
    #pragma unroll
    for (int s = 128; s > 0; s >>= 1) {
        if (t < s) red[t] += red[t + s];
        __syncthreads();
    }
    sum = red[0];

    float inv = 1.0f / sum;
    #pragma unroll
    for (int j = 0; j < 8; j++)
        row[t + j * 256] = vals[j] * inv;
}

// ---------------- launch -------------------------------------------------------
static float* sym_addr(const void* sym)
{
    void* p = nullptr;
    cudaGetSymbolAddress(&p, sym);
    return (float*)p;
}

extern "C" void kernel_launch(void* const* d_in, const int* in_sizes, int n_in,
                              void* d_out, int out_size)
{
    const float* x    = (const float*)d_in[0];
    const int*   pos  = (const int*)  d_in[1];
    const float* mask = (const float*)d_in[2];
    const float* wq   = (const float*)d_in[3];
    const float* wk   = (const float*)d_in[4];
    const float* wv   = (const float*)d_in[5];
    const float* wo   = (const float*)d_in[6];

    float* out  = (float*)d_out;                          // [1, S, H]
    float* attn = out + (long long)B_ * S_ * H_;          // [1, NH, S, S]

    float* Q   = sym_addr(g_Q);
    float* K   = sym_addr(g_K);
    float* KT  = sym_addr(g_KT);
    float* V   = sym_addr(g_V);
    float* CTX = sym_addr(g_ctx);

    const long long SS = (long long)S_ * S_;

    // 1) projections
    gemm_kernel<<<dim3(H_ / BN, S_ / BM, 1), 256>>>(
        x, wq, Q, S_, H_, H_, H_, H_, H_, 0, 0, 0);
    gemm_kernel<<<dim3(DH_ / BN, S_ / BM, 1), 256>>>(
        x, wk, K, S_, DH_, H_, H_, DH_, DH_, 0, 0, 0);
    gemm_kernel<<<dim3(DH_ / BN, S_ / BM, 1), 256>>>(
        x, wv, V, S_, DH_, H_, H_, DH_, DH_, 0, 0, 0);

    // 2) RoPE
    {
        long long tq = (long long)S_ * NH_ * (DH_ / 2);
        rope_kernel<<<(unsigned)((tq + 255) / 256), 256>>>(Q, pos, NH_, NH_ * DH_);
        long long tk = (long long)S_ * 1 * (DH_ / 2);
        rope_kernel<<<(unsigned)((tk + 255) / 256), 256>>>(K, pos, 1, DH_);
    }

    // 3) K transpose (after RoPE)
    transpose_kernel<<<dim3(DH_ / 32, S_ / 32), dim3(32, 8)>>>(K, KT, S_, DH_);

    // 4) scores: per head h, attn_h = Q_h (S x DH, lda=H) @ KT (DH x S)
    gemm_kernel<<<dim3(S_ / BN, S_ / BM, NH_), 256>>>(
        Q, KT, attn, S_, S_, DH_, H_, S_, S_, DH_, 0, SS);

    // 5) scale + mask + softmax (in place, writes final attn output)
    softmax_kernel<<<dim3(S_, NH_), 256>>>(attn, mask);

    // 6) ctx: per head h, ctx[:, h*DH:(h+1)*DH] = attn_h (S x S) @ V (S x DH)
    gemm_kernel<<<dim3(DH_ / BN, S_ / BM, NH_), 256>>>(
        attn, V, CTX, S_, DH_, S_, S_, DH_, H_, SS, 0, DH_);

    // 7) out = ctx (S x H) @ w_o (H x H)
    gemm_kernel<<<dim3(H_ / BN, S_ / BM, 1), 256>>>(
        CTX, wo, out, S_, H_, H_, H_, H_, H_, 0, 0, 0);
}

// round 2
// speedup vs baseline: 1.7138x; 1.7138x over previous
#include <cuda_runtime.h>
#include <cuda_bf16.h>
#include <cstdint>
#include <math.h>

// Problem constants
#define B_  1
#define S_  2048
#define H_  2048
#define NH_ 8
#define DH_ 256
#define SCALE_ 0.0625f   // 256^-0.5

// ---------------- scratch (device globals; no allocation allowed) -------------
__device__ float g_Q [S_ * (NH_ * DH_)];   // 2048 x 2048
__device__ float g_K [S_ * DH_];           // 2048 x 256
__device__ float g_KT[DH_ * S_];           // 256  x 2048
__device__ float g_V [S_ * DH_];           // 2048 x 256
__device__ float g_ctx[S_ * (NH_ * DH_)];  // 2048 x 2048

// =================================================================================
// Large-tile fp32 GEMM: 128x128x16, 256 threads, 8x8/thread (split 4+4),
// double-buffered smem with register-staged prefetch.
// C[b] = A[b](MxK, lda) * B[b](KxN, ldb)
// Requires M%128==0, N%128==0, K%16==0, 16B-aligned rows.
// =================================================================================
#define TBM 128
#define TBN 128
#define TBK 16

__global__ __launch_bounds__(256, 2)
void gemm128_kernel(const float* __restrict__ A,
                    const float* __restrict__ B,
                    float* __restrict__ C,
                    int M, int N, int K,
                    int lda, int ldb, int ldc,
                    long long aStride, long long bStride, long long cStride)
{
    const int batch = blockIdx.z;
    A += (long long)batch * aStride;
    B += (long long)batch * bStride;
    C += (long long)batch * cStride;

    __shared__ float As[2][TBK][TBM];   // k-major A tile
    __shared__ float Bs[2][TBK][TBN];

    const int tid = threadIdx.x;
    const int tx  = tid & 15;          // 0..15
    const int ty  = tid >> 4;          // 0..15
    const int rowBase = blockIdx.y * TBM;
    const int colBase = blockIdx.x * TBN;

    // A tile loads: 128x16 floats = 2 float4 per thread
    const int amRow = tid >> 2;          // 0..63 (+64 for second)
    const int akCol = (tid & 3) << 2;    // 0,4,8,12
    // B tile loads: 16x128 floats = 2 float4 per thread
    const int bkRow = tid >> 4;          // 0..15
    const int bnCol = (tid & 15) << 3;   // 0,8,...,120

    const float* Aptr0 = A + (long long)(rowBase + amRow)      * lda + akCol;
    const float* Aptr1 = A + (long long)(rowBase + amRow + 64) * lda + akCol;
    const float* Bptr  = B + (long long)bkRow * ldb + colBase + bnCol;

    float acc[2][2][4][4] = {};

    // --- preload tile 0 into buffer 0 ---
    {
        float4 a0 = *(const float4*)(Aptr0);
        float4 a1 = *(const float4*)(Aptr1);
        float4 b0 = *(const float4*)(Bptr);
        float4 b1 = *(const float4*)(Bptr + 4);
        As[0][akCol + 0][amRow]      = a0.x;
        As[0][akCol + 1][amRow]      = a0.y;
        As[0][akCol + 2][amRow]      = a0.z;
        As[0][akCol + 3][amRow]      = a0.w;
        As[0][akCol + 0][amRow + 64] = a1.x;
        As[0][akCol + 1][amRow + 64] = a1.y;
        As[0][akCol + 2][amRow + 64] = a1.z;
        As[0][akCol + 3][amRow + 64] = a1.w;
        *(float4*)&Bs[0][bkRow][bnCol]     = b0;
        *(float4*)&Bs[0][bkRow][bnCol + 4] = b1;
    }
    __syncthreads();

    int buf = 0;
    for (int kt = 0; kt < K; kt += TBK) {
        const bool more = (kt + TBK) < K;
        float4 nA0, nA1, nB0, nB1;
        if (more) {
            nA0 = *(const float4*)(Aptr0 + kt + TBK);
            nA1 = *(const float4*)(Aptr1 + kt + TBK);
            nB0 = *(const float4*)(Bptr + (long long)(kt + TBK) * ldb);
            nB1 = *(const float4*)(Bptr + (long long)(kt + TBK) * ldb + 4);
        }

        // --- compute on current buffer ---
        #pragma unroll
        for (int kk = 0; kk < TBK; kk++) {
            float4 af0 = *(const float4*)&As[buf][kk][ty * 4];
            float4 af1 = *(const float4*)&As[buf][kk][ty * 4 + 64];
            float4 bf0 = *(const float4*)&Bs[buf][kk][tx * 4];
            float4 bf1 = *(const float4*)&Bs[buf][kk][tx * 4 + 64];
            const float ar[2][4] = {{af0.x, af0.y, af0.z, af0.w},
                                    {af1.x, af1.y, af1.z, af1.w}};
            const float br[2][4] = {{bf0.x, bf0.y, bf0.z, bf0.w},
                                    {bf1.x, bf1.y, bf1.z, bf1.w}};
            #pragma unroll
            for (int rh = 0; rh < 2; rh++)
                #pragma unroll
                for (int ch = 0; ch < 2; ch++)
                    #pragma unroll
                    for (int i = 0; i < 4; i++)
                        #pragma unroll
                        for (int j = 0; j < 4; j++)
                            acc[rh][ch][i][j] = fmaf(ar[rh][i], br[ch][j], acc[rh][ch][i][j]);
        }

        // --- stage next tile into the other buffer ---
        if (more) {
            int nb = buf ^ 1;
            As[nb][akCol + 0][amRow]      = nA0.x;
            As[nb][akCol + 1][amRow]      = nA0.y;
            As[nb][akCol + 2][amRow]      = nA0.z;
            As[nb][akCol + 3][amRow]      = nA0.w;
            As[nb][akCol + 0][amRow + 64] = nA1.x;
            As[nb][akCol + 1][amRow + 64] = nA1.y;
            As[nb][akCol + 2][amRow + 64] = nA1.z;
            As[nb][akCol + 3][amRow + 64] = nA1.w;
            *(float4*)&Bs[nb][bkRow][bnCol]     = nB0;
            *(float4*)&Bs[nb][bkRow][bnCol + 4] = nB1;
        }
        __syncthreads();
        buf ^= 1;
    }

    // --- epilogue: vectorized stores ---
    #pragma unroll
    for (int rh = 0; rh < 2; rh++) {
        #pragma unroll
        for (int i = 0; i < 4; i++) {
            const int row = rowBase + rh * 64 + ty * 4 + i;
            float* Cp = C + (long long)row * ldc + colBase;
            #pragma unroll
            for (int ch = 0; ch < 2; ch++) {
                float4 v = make_float4(acc[rh][ch][i][0], acc[rh][ch][i][1],
                                       acc[rh][ch][i][2], acc[rh][ch][i][3]);
                *(float4*)(Cp + ch * 64 + tx * 4) = v;
            }
        }
    }
}

// =================================================================================
// Small-tile fp32 GEMM (64x64x16) — kept for narrow K/V projections (N=256),
// where 128-wide tiles would leave the chip under-occupied.
// =================================================================================
#define BM 64
#define BN 64
#define BK 16

__global__ void gemm_kernel(const float* __restrict__ A,
                            const float* __restrict__ B,
                            float* __restrict__ C,
                            int M, int N, int K,
                            int lda, int ldb, int ldc,
                            long long aStride, long long bStride, long long cStride)
{
    const int batch = blockIdx.z;
    A += (long long)batch * aStride;
    B += (long long)batch * bStride;
    C += (long long)batch * cStride;

    __shared__ float As[BM][BK + 1];
    __shared__ float Bs[BK][BN + 1];

    const int tid = threadIdx.x;
    const int tx  = tid & 15;
    const int ty  = tid >> 4;
    const int rowBase = blockIdx.y * BM;
    const int colBase = blockIdx.x * BN;

    float acc[4][4] = {};

    const int aIdx = tid * 4;
    const int am   = aIdx / BK;
    const int ak   = aIdx % BK;
    const int bIdx = tid * 4;
    const int bk   = bIdx / BN;
    const int bn   = bIdx % BN;

    for (int kt = 0; kt < K; kt += BK) {
        const float* Ap = A + (long long)(rowBase + am) * lda + (kt + ak);
        #pragma unroll
        for (int u = 0; u < 4; u++) As[am][ak + u] = Ap[u];

        const float* Bp = B + (long long)(kt + bk) * ldb + (colBase + bn);
        #pragma unroll
        for (int u = 0; u < 4; u++) Bs[bk][bn + u] = Bp[u];

        __syncthreads();

        #pragma unroll
        for (int kk = 0; kk < BK; kk++) {
            float a[4], b[4];
            #pragma unroll
            for (int i = 0; i < 4; i++) a[i] = As[ty * 4 + i][kk];
            #pragma unroll
            for (int j = 0; j < 4; j++) b[j] = Bs[kk][tx * 4 + j];
            #pragma unroll
            for (int i = 0; i < 4; i++)
                #pragma unroll
                for (int j = 0; j < 4; j++)
                    acc[i][j] = fmaf(a[i], b[j], acc[i][j]);
        }
        __syncthreads();
    }

    #pragma unroll
    for (int i = 0; i < 4; i++) {
        float* Cp = C + (long long)(rowBase + ty * 4 + i) * ldc + colBase + tx * 4;
        #pragma unroll
        for (int j = 0; j < 4; j++) Cp[j] = acc[i][j];
    }
}

// ---------------- RoPE --------------------------------------------------------
__global__ void rope_kernel(float* __restrict__ buf, const int* __restrict__ pos,
                            int nHeads, int rowStride)
{
    long long idx = (long long)blockIdx.x * blockDim.x + threadIdx.x;
    const long long total = (long long)S_ * nHeads * (DH_ / 2);
    if (idx >= total) return;
    int d = (int)(idx % (DH_ / 2));
    int h = (int)((idx / (DH_ / 2)) % nHeads);
    int s = (int)(idx / ((long long)(DH_ / 2) * nHeads));

    float p = (float)pos[s];
    float inv = exp2f(-((float)(2 * d) / (float)DH_) * log2f(10000.0f));
    float ang = p * inv;
    float sn, cs;
    sincosf(ang, &sn, &cs);

    float* base = buf + (long long)s * rowStride + h * DH_;
    float a = base[d];
    float b = base[d + 128];
    base[d]       = a * cs - b * sn;
    base[d + 128] = b * cs + a * sn;
}

// ---------------- transpose (K: SxDH -> KT: DHxS) ------------------------------
__global__ void transpose_kernel(const float* __restrict__ in, float* __restrict__ out,
                                 int R, int C)
{
    __shared__ float tile[32][33];
    int c0 = blockIdx.x * 32;
    int r0 = blockIdx.y * 32;
    int tx = threadIdx.x, ty = threadIdx.y;   // 32 x 8
    #pragma unroll
    for (int i = 0; i < 32; i += 8)
        tile[ty + i][tx] = in[(long long)(r0 + ty + i) * C + (c0 + tx)];
    __syncthreads();
    #pragma unroll
    for (int i = 0; i < 32; i += 8)
        out[(long long)(c0 + ty + i) * R + (r0 + tx)] = tile[tx][ty + i];
}

// ---------------- scale + mask + softmax (in place on attn) --------------------
__global__ void softmax_kernel(float* __restrict__ attn, const float* __restrict__ mask)
{
    const int i = blockIdx.x;
    const int h = blockIdx.y;
    float* row = attn + ((long long)h * S_ + i) * S_;
    const float* mrow = mask + (long long)i * S_;
    const int t = threadIdx.x;

    float vals[8];
    float mx = -INFINITY;
    #pragma unroll
    for (int j = 0; j < 8; j++) {
        int col = t + j * 256;
        float v = row[col] * SCALE_ + mrow[col];
        vals[j] = v;
        mx = fmaxf(mx, v);
    }

    __shared__ float red[256];
    red[t] = mx;
    __syncthreads();
    #pragma unroll
    for (int s = 128; s > 0; s >>= 1) {
        if (t < s) red[t] = fmaxf(red[t], red[t + s]);
        __syncthreads();
    }
    mx = red[0];
    __syncthreads();

    float sum = 0.0f;
    #pragma unroll
    for (int j = 0; j < 8; j++) {
        vals[j] = __expf(vals[j] - mx);
        sum += vals[j];
    }
    red[t] = sum;
    __syncthreads();
    #pragma unroll
    for (int s = 128; s > 0; s >>= 1) {
        if (t < s) red[t] += red[t + s];
        __syncthreads();
    }
    sum = red[0];

    float inv = 1.0f / sum;
    #pragma unroll
    for (int j = 0; j < 8; j++)
        row[t + j * 256] = vals[j] * inv;
}

// ---------------- launch -------------------------------------------------------
static float* sym_addr(const void* sym)
{
    void* p = nullptr;
    cudaGetSymbolAddress(&p, sym);
    return (float*)p;
}

extern "C" void kernel_launch(void* const* d_in, const int* in_sizes, int n_in,
                              void* d_out, int out_size)
{
    const float* x    = (const float*)d_in[0];
    const int*   pos  = (const int*)  d_in[1];
    const float* mask = (const float*)d_in[2];
    const float* wq   = (const float*)d_in[3];
    const float* wk   = (const float*)d_in[4];
    const float* wv   = (const float*)d_in[5];
    const float* wo   = (const float*)d_in[6];

    float* out  = (float*)d_out;                          // [1, S, H]
    float* attn = out + (long long)B_ * S_ * H_;          // [1, NH, S, S]

    float* Q   = sym_addr(g_Q);
    float* K   = sym_addr(g_K);
    float* KT  = sym_addr(g_KT);
    float* V   = sym_addr(g_V);
    float* CTX = sym_addr(g_ctx);

    const long long SS = (long long)S_ * S_;

    // 1) projections — Q uses the big-tile kernel; K/V stay small-tile for occupancy
    gemm128_kernel<<<dim3(H_ / TBN, S_ / TBM, 1), 256>>>(
        x, wq, Q, S_, H_, H_, H_, H_, H_, 0, 0, 0);
    gemm_kernel<<<dim3(DH_ / BN, S_ / BM, 1), 256>>>(
        x, wk, K, S_, DH_, H_, H_, DH_, DH_, 0, 0, 0);
    gemm_kernel<<<dim3(DH_ / BN, S_ / BM, 1), 256>>>(
        x, wv, V, S_, DH_, H_, H_, DH_, DH_, 0, 0, 0);

    // 2) RoPE
    {
        long long tq = (long long)S_ * NH_ * (DH_ / 2);
        rope_kernel<<<(unsigned)((tq + 255) / 256), 256>>>(Q, pos, NH_, NH_ * DH_);
        long long tk = (long long)S_ * 1 * (DH_ / 2);
        rope_kernel<<<(unsigned)((tk + 255) / 256), 256>>>(K, pos, 1, DH_);
    }

    // 3) K transpose (after RoPE)
    transpose_kernel<<<dim3(DH_ / 32, S_ / 32), dim3(32, 8)>>>(K, KT, S_, DH_);

    // 4) scores: per head h, attn_h = Q_h (S x DH, lda=H) @ KT (DH x S)
    gemm128_kernel<<<dim3(S_ / TBN, S_ / TBM, NH_), 256>>>(
        Q, KT, attn, S_, S_, DH_, H_, S_, S_, DH_, 0, SS);

    // 5) scale + mask + softmax (in place, writes final attn output)
    softmax_kernel<<<dim3(S_, NH_), 256>>>(attn, mask);

    // 6) ctx: per head h, ctx[:, h*DH:(h+1)*DH] = attn_h (S x S) @ V (S x DH)
    gemm128_kernel<<<dim3(DH_ / TBN, S_ / TBM, NH_), 256>>>(
        attn, V, CTX, S_, DH_, S_, S_, DH_, H_, SS, 0, DH_);

    // 7) out = ctx (S x H) @ w_o (H x H)
    gemm128_kernel<<<dim3(H_ / TBN, S_ / TBM, 1), 256>>>(
        CTX, wo, out, S_, H_, H_, H_, H_, H_, 0, 0, 0);
}

// round 4
// speedup vs baseline: 3.1184x; 1.8196x over previous
#include <cuda_runtime.h>
#include <cuda_bf16.h>
#include <cstdint>
#include <math.h>

// Problem constants
#define B_  1
#define S_  2048
#define H_  2048
#define NH_ 8
#define DH_ 256
#define SCALE_ 0.0625f   // 256^-0.5

typedef __nv_bfloat16 bf16;

// ================= helpers =====================================================
__device__ __forceinline__ uint32_t smem_to_u32(const void* smem_ptr) {
    uint32_t addr;
    asm("{ .reg .u64 tmp; cvta.to.shared.u64 tmp, %1; cvt.u32.u64 %0, tmp; }"
        : "=r"(addr) : "l"(smem_ptr));
    return addr;
}

__device__ __forceinline__ void cp_async16(uint32_t dst, const void* src) {
    asm volatile("cp.async.cg.shared.global [%0], [%1], 16;\n"
                 :: "r"(dst), "l"(src) : "memory");
}

__device__ __forceinline__ void ldsm_x4(uint32_t r[4], uint32_t addr) {
    asm volatile("ldmatrix.sync.aligned.m8n8.x4.shared.b16 {%0,%1,%2,%3}, [%4];"
                 : "=r"(r[0]), "=r"(r[1]), "=r"(r[2]), "=r"(r[3]) : "r"(addr));
}

__device__ __forceinline__ void ldsm_x2(uint32_t r[2], uint32_t addr) {
    asm volatile("ldmatrix.sync.aligned.m8n8.x2.shared.b16 {%0,%1}, [%2];"
                 : "=r"(r[0]), "=r"(r[1]) : "r"(addr));
}

__device__ __forceinline__ void mma_bf16(float acc[4], const uint32_t a[4], const uint32_t b[2]) {
    asm volatile(
        "mma.sync.aligned.m16n8k16.row.col.f32.bf16.bf16.f32 "
        "{%0,%1,%2,%3}, {%4,%5,%6,%7}, {%8,%9}, {%0,%1,%2,%3};"
        : "+f"(acc[0]), "+f"(acc[1]), "+f"(acc[2]), "+f"(acc[3])
        : "r"(a[0]), "r"(a[1]), "r"(a[2]), "r"(a[3]), "r"(b[0]), "r"(b[1]));
}

// ================= scratch (device globals; no allocation) ====================
__device__ __align__(128) float g_Q  [S_ * H_];
__device__ __align__(128) float g_K  [S_ * DH_];
__device__ __align__(128) float g_V  [S_ * DH_];
__device__ __align__(128) float g_ctx[S_ * H_];

__device__ __align__(128) bf16 g_xhi [S_ * H_];
__device__ __align__(128) bf16 g_xlo [S_ * H_];
__device__ __align__(128) bf16 g_wqThi[H_ * H_];
__device__ __align__(128) bf16 g_wqTlo[H_ * H_];
__device__ __align__(128) bf16 g_wkThi[DH_ * H_];
__device__ __align__(128) bf16 g_wkTlo[DH_ * H_];
__device__ __align__(128) bf16 g_wvThi[DH_ * H_];
__device__ __align__(128) bf16 g_wvTlo[DH_ * H_];
__device__ __align__(128) bf16 g_woThi[H_ * H_];
__device__ __align__(128) bf16 g_woTlo[H_ * H_];
__device__ __align__(128) bf16 g_qhi [S_ * H_];
__device__ __align__(128) bf16 g_qlo [S_ * H_];
__device__ __align__(128) bf16 g_khi [S_ * DH_];
__device__ __align__(128) bf16 g_klo [S_ * DH_];
__device__ __align__(128) bf16 g_vthi[DH_ * S_];
__device__ __align__(128) bf16 g_vtlo[DH_ * S_];
__device__ __align__(128) bf16 g_phi [(long long)NH_ * S_ * S_];
__device__ __align__(128) bf16 g_plo [(long long)NH_ * S_ * S_];
__device__ __align__(128) bf16 g_chi [S_ * H_];
__device__ __align__(128) bf16 g_clo [S_ * H_];

// ================= split-bf16 mma.sync GEMM ===================================
// C = (Ahi+Alo) @ (Bhi+Blo)^T  via 3 HMMA passes (hh + hl + lh), fp32 accum.
// A: M x K (K-major, lda); B: N x K (K-major, ldb); C: M x N fp32 (ldc).
// CTA tile: 128 x (NT8*32).  512 threads = 16 warps in 4(m) x 4(n).
// Warp tile: 32 x (NT8*8).  K-chunk 32, cp.async double-buffered.
template<int NT8>
__global__ __launch_bounds__(512, 1)
void mma_gemm(const bf16* __restrict__ Ahi, const bf16* __restrict__ Alo,
              const bf16* __restrict__ Bhi, const bf16* __restrict__ Blo,
              float* __restrict__ C,
              int K, int lda, int ldb, int ldc,
              long long aStride, long long bStride, long long cStride)
{
    constexpr int TN     = NT8 * 32;       // CTA N tile: 128 or 64
    constexpr int ROW    = 40;             // padded bf16 per smem row (80B)
    constexpr int A_TILE = 128 * ROW;      // bf16 elems per A operand tile
    constexpr int B_TILE = TN * ROW;
    constexpr int STAGE  = 2 * A_TILE + 2 * B_TILE;  // elems per stage

    extern __shared__ bf16 smem[];
    const uint32_t sbase = smem_to_u32(smem);

    const int tid  = threadIdx.x;
    const int wid  = tid >> 5;
    const int lane = tid & 31;
    const int wm   = wid & 3;              // m warp 0..3 -> rows 32*wm
    const int wn   = wid >> 2;             // n warp 0..3 -> cols (NT8*8)*wn
    const int rowBase = blockIdx.y * 128;
    const int colBase = blockIdx.x * TN;

    Ahi += (long long)blockIdx.z * aStride;
    Alo += (long long)blockIdx.z * aStride;
    Bhi += (long long)blockIdx.z * bStride;
    Blo += (long long)blockIdx.z * bStride;
    C   += (long long)blockIdx.z * cStride;

    float acc[2][NT8][4] = {};

    const int nStages = K >> 5;

    // loader: thread -> (row 0..127, 16B chunk 0..3)
    const int lrow = tid >> 2;
    const int lch  = tid & 3;

    auto issue = [&](int s) {
        const int buf = s & 1;
        const uint32_t sb = sbase + (uint32_t)buf * STAGE * 2;
        const int kt = s << 5;
        {
            const long long g = (long long)(rowBase + lrow) * lda + kt + lch * 8;
            const uint32_t d = sb + (uint32_t)(lrow * ROW + lch * 8) * 2;
            cp_async16(d,              Ahi + g);
            cp_async16(d + A_TILE * 2, Alo + g);
        }
        if (tid < TN * 4) {
            const long long g = (long long)(colBase + lrow) * ldb + kt + lch * 8;
            const uint32_t d = sb + (uint32_t)(2 * A_TILE + lrow * ROW + lch * 8) * 2;
            cp_async16(d,              Bhi + g);
            cp_async16(d + B_TILE * 2, Blo + g);
        }
        asm volatile("cp.async.commit_group;\n" ::: "memory");
    };

    issue(0);

    for (int s = 0; s < nStages; s++) {
        if (s + 1 < nStages) {
            issue(s + 1);
            asm volatile("cp.async.wait_group 1;\n" ::: "memory");
        } else {
            asm volatile("cp.async.wait_group 0;\n" ::: "memory");
        }
        __syncthreads();

        const uint32_t sb = sbase + (uint32_t)(s & 1) * STAGE * 2;
        const uint32_t sA = sb;
        const uint32_t sB = sb + 2 * A_TILE * 2;

        #pragma unroll
        for (int kk = 0; kk < 2; kk++) {
            // ---- A fragments (hi & lo), 2 m16 tiles per warp ----
            uint32_t ah[2][4], al[2][4];
            const int arow = wm * 32 + (lane & 15);
            const int acol = kk * 16 + ((lane >> 4) << 3);
            #pragma unroll
            for (int mt = 0; mt < 2; mt++) {
                const uint32_t addr = sA + (uint32_t)((arow + mt * 16) * ROW + acol) * 2;
                ldsm_x4(ah[mt], addr);
                ldsm_x4(al[mt], addr + A_TILE * 2);
            }
            // ---- B fragments (hi & lo), NT8 n8 tiles per warp ----
            uint32_t bh[NT8][2], bl[NT8][2];
            const int lane16 = lane & 15;
            const int brow = wn * (NT8 * 8) + (lane16 & 7);
            const int bcol = kk * 16 + ((lane16 >> 3) << 3);
            #pragma unroll
            for (int nt = 0; nt < NT8; nt++) {
                const uint32_t addr = sB + (uint32_t)((brow + nt * 8) * ROW + bcol) * 2;
                ldsm_x2(bh[nt], addr);
                ldsm_x2(bl[nt], addr + B_TILE * 2);
            }
            // ---- 3-pass split MMA ----
            #pragma unroll
            for (int mt = 0; mt < 2; mt++)
                #pragma unroll
                for (int nt = 0; nt < NT8; nt++) {
                    mma_bf16(acc[mt][nt], ah[mt], bh[nt]);
                    mma_bf16(acc[mt][nt], ah[mt], bl[nt]);
                    mma_bf16(acc[mt][nt], al[mt], bh[nt]);
                }
        }
        __syncthreads();
    }

    // ---- epilogue: direct fp32 stores ----
    const int erow  = rowBase + wm * 32 + (lane >> 2);
    const int ecol0 = colBase + wn * (NT8 * 8) + (lane & 3) * 2;
    #pragma unroll
    for (int mt = 0; mt < 2; mt++) {
        #pragma unroll
        for (int nt = 0; nt < NT8; nt++) {
            const int r = erow + mt * 16;
            const int c = ecol0 + nt * 8;
            float2 v0 = make_float2(acc[mt][nt][0], acc[mt][nt][1]);
            float2 v1 = make_float2(acc[mt][nt][2], acc[mt][nt][3]);
            *(float2*)&C[(long long)r * ldc + c]       = v0;
            *(float2*)&C[(long long)(r + 8) * ldc + c] = v1;
        }
    }
}

// ================= fp32 -> bf16 hi/lo split ===================================
__global__ void split_kernel(const float* __restrict__ in,
                             bf16* __restrict__ hi, bf16* __restrict__ lo,
                             long long n)
{
    long long i = (long long)blockIdx.x * blockDim.x + threadIdx.x;
    if (i >= n) return;
    float v = in[i];
    bf16 h = __float2bfloat16(v);
    hi[i] = h;
    lo[i] = __float2bfloat16(v - __bfloat162float(h));
}

// transpose + split: in[R][C] fp32 -> hiT/loT [C][R] bf16
__global__ void tsplit_kernel(const float* __restrict__ in,
                              bf16* __restrict__ hiT, bf16* __restrict__ loT,
                              int R, int C)
{
    __shared__ float tile[32][33];
    const int c0 = blockIdx.x * 32;
    const int r0 = blockIdx.y * 32;
    const int tx = threadIdx.x, ty = threadIdx.y;  // 32 x 8
    #pragma unroll
    for (int i = 0; i < 32; i += 8)
        tile[ty + i][tx] = in[(long long)(r0 + ty + i) * C + (c0 + tx)];
    __syncthreads();
    #pragma unroll
    for (int i = 0; i < 32; i += 8) {
        float v = tile[tx][ty + i];
        bf16 h = __float2bfloat16(v);
        long long o = (long long)(c0 + ty + i) * R + (r0 + tx);
        hiT[o] = h;
        loT[o] = __float2bfloat16(v - __bfloat162float(h));
    }
}

// ================= RoPE (reads fp32, emits bf16 hi/lo) ========================
__global__ void rope_split_kernel(const float* __restrict__ src,
                                  bf16* __restrict__ hi, bf16* __restrict__ lo,
                                  const int* __restrict__ pos,
                                  int nHeads, int rowStride)
{
    long long idx = (long long)blockIdx.x * blockDim.x + threadIdx.x;
    const long long total = (long long)S_ * nHeads * (DH_ / 2);
    if (idx >= total) return;
    int d = (int)(idx % (DH_ / 2));
    int h = (int)((idx / (DH_ / 2)) % nHeads);
    int s = (int)(idx / ((long long)(DH_ / 2) * nHeads));

    float p = (float)pos[s];
    float inv = exp2f(-((float)(2 * d) / (float)DH_) * log2f(10000.0f));
    float ang = p * inv;
    float sn, cs;
    sincosf(ang, &sn, &cs);

    const long long base = (long long)s * rowStride + h * DH_;
    float a = src[base + d];
    float b = src[base + d + 128];
    float ra = a * cs - b * sn;
    float rb = b * cs + a * sn;

    bf16 ha = __float2bfloat16(ra);
    bf16 hb = __float2bfloat16(rb);
    hi[base + d]       = ha;
    hi[base + d + 128] = hb;
    lo[base + d]       = __float2bfloat16(ra - __bfloat162float(ha));
    lo[base + d + 128] = __float2bfloat16(rb - __bfloat162float(hb));
}

// ================= scale + mask + softmax (fp32 out + bf16 hi/lo) =============
__global__ void softmax_kernel(float* __restrict__ attn, const float* __restrict__ mask,
                               bf16* __restrict__ phi, bf16* __restrict__ plo)
{
    const int i = blockIdx.x;
    const int h = blockIdx.y;
    const long long rowOff = ((long long)h * S_ + i) * S_;
    float* row = attn + rowOff;
    const float* mrow = mask + (long long)i * S_;
    const int t = threadIdx.x;

    float vals[8];
    float mx = -INFINITY;
    #pragma unroll
    for (int j = 0; j < 8; j++) {
        int col = t + j * 256;
        float v = row[col] * SCALE_ + mrow[col];
        vals[j] = v;
        mx = fmaxf(mx, v);
    }

    __shared__ float red[256];
    red[t] = mx;
    __syncthreads();
    #pragma unroll
    for (int s = 128; s > 0; s >>= 1) {
        if (t < s) red[t] = fmaxf(red[t], red[t + s]);
        __syncthreads();
    }
    mx = red[0];
    __syncthreads();

    float sum = 0.0f;
    #pragma unroll
    for (int j = 0; j < 8; j++) {
        vals[j] = __expf(vals[j] - mx);
        sum += vals[j];
    }
    red[t] = sum;
    __syncthreads();
    #pragma unroll
    for (int s = 128; s > 0; s >>= 1) {
        if (t < s) red[t] += red[t + s];
        __syncthreads();
    }
    sum = red[0];

    float inv = 1.0f / sum;
    #pragma unroll
    for (int j = 0; j < 8; j++) {
        int col = t + j * 256;
        float p = vals[j] * inv;
        row[col] = p;
        bf16 hp = __float2bfloat16(p);
        phi[rowOff + col] = hp;
        plo[rowOff + col] = __float2bfloat16(p - __bfloat162float(hp));
    }
}

// ================= launch ======================================================
static void* sym_addr(const void* sym)
{
    void* p = nullptr;
    cudaGetSymbolAddress(&p, sym);
    return p;
}

extern "C" void kernel_launch(void* const* d_in, const int* in_sizes, int n_in,
                              void* d_out, int out_size)
{
    const float* x    = (const float*)d_in[0];
    const int*   pos  = (const int*)  d_in[1];
    const float* mask = (const float*)d_in[2];
    const float* wq   = (const float*)d_in[3];
    const float* wk   = (const float*)d_in[4];
    const float* wv   = (const float*)d_in[5];
    const float* wo   = (const float*)d_in[6];

    float* out  = (float*)d_out;
    float* attn = out + (long long)B_ * S_ * H_;

    float* Qf  = (float*)sym_addr(g_Q);
    float* Kf  = (float*)sym_addr(g_K);
    float* Vf  = (float*)sym_addr(g_V);
    float* CTX = (float*)sym_addr(g_ctx);

    bf16* xhi   = (bf16*)sym_addr(g_xhi);
    bf16* xlo   = (bf16*)sym_addr(g_xlo);
    bf16* wqThi = (bf16*)sym_addr(g_wqThi);
    bf16* wqTlo = (bf16*)sym_addr(g_wqTlo);
    bf16* wkThi = (bf16*)sym_addr(g_wkThi);
    bf16* wkTlo = (bf16*)sym_addr(g_wkTlo);
    bf16* wvThi = (bf16*)sym_addr(g_wvThi);
    bf16* wvTlo = (bf16*)sym_addr(g_wvTlo);
    bf16* woThi = (bf16*)sym_addr(g_woThi);
    bf16* woTlo = (bf16*)sym_addr(g_woTlo);
    bf16* qhi   = (bf16*)sym_addr(g_qhi);
    bf16* qlo   = (bf16*)sym_addr(g_qlo);
    bf16* khi   = (bf16*)sym_addr(g_khi);
    bf16* klo   = (bf16*)sym_addr(g_klo);
    bf16* vthi  = (bf16*)sym_addr(g_vthi);
    bf16* vtlo  = (bf16*)sym_addr(g_vtlo);
    bf16* phi   = (bf16*)sym_addr(g_phi);
    bf16* plo   = (bf16*)sym_addr(g_plo);
    bf16* chi   = (bf16*)sym_addr(g_chi);
    bf16* clo   = (bf16*)sym_addr(g_clo);

    // dynamic smem sizes (bytes): 2 stages of (2*A + 2*B) bf16 tiles
    const int smem128 = 2 * (2 * 128 * 40 + 2 * 128 * 40) * 2;  // 81920
    const int smem64  = 2 * (2 * 128 * 40 + 2 *  64 * 40) * 2;  // 61440
    cudaFuncSetAttribute(mma_gemm<4>, cudaFuncAttributeMaxDynamicSharedMemorySize, smem128);
    cudaFuncSetAttribute(mma_gemm<2>, cudaFuncAttributeMaxDynamicSharedMemorySize, smem64);

    const long long SS  = (long long)S_ * S_;
    const long long nSH = (long long)S_ * H_;

    // ---- operand prep ----
    split_kernel<<<(unsigned)((nSH + 255) / 256), 256>>>(x, xhi, xlo, nSH);
    tsplit_kernel<<<dim3(H_ / 32,  H_ / 32), dim3(32, 8)>>>(wq, wqThi, wqTlo, H_, H_);
    tsplit_kernel<<<dim3(DH_ / 32, H_ / 32), dim3(32, 8)>>>(wk, wkThi, wkTlo, H_, DH_);
    tsplit_kernel<<<dim3(DH_ / 32, H_ / 32), dim3(32, 8)>>>(wv, wvThi, wvTlo, H_, DH_);
    tsplit_kernel<<<dim3(H_ / 32,  H_ / 32), dim3(32, 8)>>>(wo, woThi, woTlo, H_, H_);

    // ---- projections ----
    mma_gemm<4><<<dim3(H_ / 128, S_ / 128, 1), 512, smem128>>>(
        xhi, xlo, wqThi, wqTlo, Qf, H_, H_, H_, H_, 0, 0, 0);
    mma_gemm<2><<<dim3(DH_ / 64, S_ / 128, 1), 512, smem64>>>(
        xhi, xlo, wkThi, wkTlo, Kf, H_, H_, H_, DH_, 0, 0, 0);
    mma_gemm<2><<<dim3(DH_ / 64, S_ / 128, 1), 512, smem64>>>(
        xhi, xlo, wvThi, wvTlo, Vf, H_, H_, H_, DH_, 0, 0, 0);

    // ---- RoPE -> bf16 hi/lo ----
    rope_split_kernel<<<(unsigned)(((long long)S_ * NH_ * 128 + 255) / 256), 256>>>(
        Qf, qhi, qlo, pos, NH_, H_);
    rope_split_kernel<<<(unsigned)(((long long)S_ * 128 + 255) / 256), 256>>>(
        Kf, khi, klo, pos, 1, DH_);

    // ---- V transpose + split ----
    tsplit_kernel<<<dim3(DH_ / 32, S_ / 32), dim3(32, 8)>>>(Vf, vthi, vtlo, S_, DH_);

    // ---- scores: attn_h = Q_h @ K^T ----
    mma_gemm<4><<<dim3(S_ / 128, S_ / 128, NH_), 512, smem128>>>(
        qhi, qlo, khi, klo, attn, DH_, H_, DH_, S_, DH_, 0, SS);

    // ---- softmax ----
    softmax_kernel<<<dim3(S_, NH_), 256>>>(attn, mask, phi, plo);

    // ---- ctx_h = P_h @ V ----
    mma_gemm<4><<<dim3(DH_ / 128, S_ / 128, NH_), 512, smem128>>>(
        phi, plo, vthi, vtlo, CTX, S_, S_, S_, H_, SS, 0, DH_);

    // ---- out = ctx @ w_o ----
    split_kernel<<<(unsigned)((nSH + 255) / 256), 256>>>(CTX, chi, clo, nSH);
    mma_gemm<4><<<dim3(H_ / 128, S_ / 128, 1), 512, smem128>>>(
        chi, clo, woThi, woTlo, out, H_, H_, H_, H_, 0, 0, 0);
}

// round 5
// speedup vs baseline: 4.0235x; 1.2902x over previous
#include <cuda_runtime.h>
#include <cuda_bf16.h>
#include <cstdint>
#include <math.h>

// Problem constants
#define B_  1
#define S_  2048
#define H_  2048
#define NH_ 8
#define DH_ 256
#define SCALE_ 0.0625f   // 256^-0.5
#define NEG_  -1000000000.0f

typedef __nv_bfloat16 bf16;

// ================= helpers =====================================================
__device__ __forceinline__ uint32_t smem_to_u32(const void* smem_ptr) {
    uint32_t addr;
    asm("{ .reg .u64 tmp; cvta.to.shared.u64 tmp, %1; cvt.u32.u64 %0, tmp; }"
        : "=r"(addr) : "l"(smem_ptr));
    return addr;
}

__device__ __forceinline__ void cp_async16(uint32_t dst, const void* src) {
    asm volatile("cp.async.cg.shared.global [%0], [%1], 16;\n"
                 :: "r"(dst), "l"(src) : "memory");
}

__device__ __forceinline__ void ldsm_x4(uint32_t r[4], uint32_t addr) {
    asm volatile("ldmatrix.sync.aligned.m8n8.x4.shared.b16 {%0,%1,%2,%3}, [%4];"
                 : "=r"(r[0]), "=r"(r[1]), "=r"(r[2]), "=r"(r[3]) : "r"(addr));
}

__device__ __forceinline__ void ldsm_x2(uint32_t r[2], uint32_t addr) {
    asm volatile("ldmatrix.sync.aligned.m8n8.x2.shared.b16 {%0,%1}, [%2];"
                 : "=r"(r[0]), "=r"(r[1]) : "r"(addr));
}

__device__ __forceinline__ void mma_bf16(float acc[4], const uint32_t a[4], const uint32_t b[2]) {
    asm volatile(
        "mma.sync.aligned.m16n8k16.row.col.f32.bf16.bf16.f32 "
        "{%0,%1,%2,%3}, {%4,%5,%6,%7}, {%8,%9}, {%0,%1,%2,%3};"
        : "+f"(acc[0]), "+f"(acc[1]), "+f"(acc[2]), "+f"(acc[3])
        : "r"(a[0]), "r"(a[1]), "r"(a[2]), "r"(a[3]), "r"(b[0]), "r"(b[1]));
}

__device__ __forceinline__ uint32_t pack_hi2(float v0, float v1) {
    bf16 h0 = __float2bfloat16(v0);
    bf16 h1 = __float2bfloat16(v1);
    return (uint32_t)__bfloat16_as_ushort(h0) | ((uint32_t)__bfloat16_as_ushort(h1) << 16);
}
__device__ __forceinline__ uint32_t pack_lo2(float v0, float v1) {
    bf16 h0 = __float2bfloat16(v0);
    bf16 h1 = __float2bfloat16(v1);
    bf16 l0 = __float2bfloat16(v0 - __bfloat162float(h0));
    bf16 l1 = __float2bfloat16(v1 - __bfloat162float(h1));
    return (uint32_t)__bfloat16_as_ushort(l0) | ((uint32_t)__bfloat16_as_ushort(l1) << 16);
}

// ================= scratch (device globals; no allocation) ====================
__device__ __align__(128) float g_Q  [S_ * H_];
__device__ __align__(128) float g_K  [S_ * DH_];
__device__ __align__(128) float g_V  [S_ * DH_];

__device__ __align__(128) bf16 g_xhi [S_ * H_];
__device__ __align__(128) bf16 g_xlo [S_ * H_];
__device__ __align__(128) bf16 g_wqThi[H_ * H_];
__device__ __align__(128) bf16 g_wqTlo[H_ * H_];
__device__ __align__(128) bf16 g_wkThi[DH_ * H_];
__device__ __align__(128) bf16 g_wkTlo[DH_ * H_];
__device__ __align__(128) bf16 g_wvThi[DH_ * H_];
__device__ __align__(128) bf16 g_wvTlo[DH_ * H_];
__device__ __align__(128) bf16 g_woThi[H_ * H_];
__device__ __align__(128) bf16 g_woTlo[H_ * H_];
__device__ __align__(128) bf16 g_qhi [S_ * H_];
__device__ __align__(128) bf16 g_qlo [S_ * H_];
__device__ __align__(128) bf16 g_khi [S_ * DH_];
__device__ __align__(128) bf16 g_klo [S_ * DH_];
__device__ __align__(128) bf16 g_vthi[DH_ * S_];
__device__ __align__(128) bf16 g_vtlo[DH_ * S_];
__device__ __align__(128) bf16 g_phi [(long long)NH_ * S_ * S_];
__device__ __align__(128) bf16 g_plo [(long long)NH_ * S_ * S_];
__device__ __align__(128) bf16 g_chi [S_ * H_];
__device__ __align__(128) bf16 g_clo [S_ * H_];

// ================= split-bf16 mma.sync GEMM ===================================
// C = (Ahi+Alo) @ (Bhi+Blo)^T  via 3 HMMA passes (hh + hl + lh), fp32 accum.
// A: M x K (K-major, lda); B: N x K (K-major, ldb).
// Output: fp32 C (if non-null) and/or bf16 hi/lo Chi/Clo (if non-null), both ldc.
// CTA: 128 x (NT8*32), 256 threads = 8 warps in 2(m) x 4(n), warp tile 64 x (NT8*8).
// mode bit0: causal tile skip (skip if colBase > rowBase+127)
// mode bit1: causal K limit   (K_eff = min(K, rowBase+128))
template<int NT8>
__global__ __launch_bounds__(256, 2)
void mma_gemm(const bf16* __restrict__ Ahi, const bf16* __restrict__ Alo,
              const bf16* __restrict__ Bhi, const bf16* __restrict__ Blo,
              float* __restrict__ C,
              bf16* __restrict__ Chi, bf16* __restrict__ Clo,
              int K, int lda, int ldb, int ldc,
              long long aStride, long long bStride, long long cStride,
              int mode)
{
    constexpr int TN     = NT8 * 32;
    constexpr int ROW    = 40;                       // padded bf16 per smem row (80B)
    constexpr int A_TILE = 128 * ROW;
    constexpr int B_TILE = TN * ROW;
    constexpr int STAGE  = 2 * A_TILE + 2 * B_TILE;

    const int rowBase = blockIdx.y * 128;
    const int colBase = blockIdx.x * TN;

    if ((mode & 1) && colBase > rowBase + 127) return;

    int Keff = K;
    if (mode & 2) Keff = min(K, rowBase + 128);

    extern __shared__ bf16 smem[];
    const uint32_t sbase = smem_to_u32(smem);

    const int tid  = threadIdx.x;
    const int wid  = tid >> 5;
    const int lane = tid & 31;
    const int wm   = wid & 1;              // m warp 0..1 -> rows 64*wm
    const int wn   = wid >> 1;             // n warp 0..3 -> cols (NT8*8)*wn

    Ahi += (long long)blockIdx.z * aStride;
    Alo += (long long)blockIdx.z * aStride;
    Bhi += (long long)blockIdx.z * bStride;
    Blo += (long long)blockIdx.z * bStride;

    float acc[4][NT8][4] = {};

    const int nStages = Keff >> 5;

    // loader: 256 threads, A: 128 rows x 4 chunks -> 2 rows/thread
    const int lrow = tid >> 2;          // 0..63
    const int lch  = tid & 3;

    auto issue = [&](int s) {
        const int buf = s & 1;
        const uint32_t sb = sbase + (uint32_t)buf * STAGE * 2;
        const int kt = s << 5;
        #pragma unroll
        for (int half = 0; half < 2; half++) {
            const int r = lrow + half * 64;
            const long long g = (long long)(rowBase + r) * lda + kt + lch * 8;
            const uint32_t d = sb + (uint32_t)(r * ROW + lch * 8) * 2;
            cp_async16(d,              Ahi + g);
            cp_async16(d + A_TILE * 2, Alo + g);
        }
        if (TN == 128) {
            #pragma unroll
            for (int half = 0; half < 2; half++) {
                const int r = lrow + half * 64;
                const long long g = (long long)(colBase + r) * ldb + kt + lch * 8;
                const uint32_t d = sb + (uint32_t)(2 * A_TILE + r * ROW + lch * 8) * 2;
                cp_async16(d,              Bhi + g);
                cp_async16(d + B_TILE * 2, Blo + g);
            }
        } else {
            const long long g = (long long)(colBase + lrow) * ldb + kt + lch * 8;
            const uint32_t d = sb + (uint32_t)(2 * A_TILE + lrow * ROW + lch * 8) * 2;
            cp_async16(d,              Bhi + g);
            cp_async16(d + B_TILE * 2, Blo + g);
        }
        asm volatile("cp.async.commit_group;\n" ::: "memory");
    };

    issue(0);

    for (int s = 0; s < nStages; s++) {
        if (s + 1 < nStages) {
            issue(s + 1);
            asm volatile("cp.async.wait_group 1;\n" ::: "memory");
        } else {
            asm volatile("cp.async.wait_group 0;\n" ::: "memory");
        }
        __syncthreads();

        const uint32_t sb = sbase + (uint32_t)(s & 1) * STAGE * 2;
        const uint32_t sA = sb;
        const uint32_t sB = sb + 2 * A_TILE * 2;

        #pragma unroll
        for (int kk = 0; kk < 2; kk++) {
            uint32_t ah[4][4], al[4][4];
            const int arow = wm * 64 + (lane & 15);
            const int acol = kk * 16 + ((lane >> 4) << 3);
            #pragma unroll
            for (int mt = 0; mt < 4; mt++) {
                const uint32_t addr = sA + (uint32_t)((arow + mt * 16) * ROW + acol) * 2;
                ldsm_x4(ah[mt], addr);
                ldsm_x4(al[mt], addr + A_TILE * 2);
            }
            uint32_t bh[NT8][2], bl[NT8][2];
            const int lane16 = lane & 15;
            const int brow = wn * (NT8 * 8) + (lane16 & 7);
            const int bcol = kk * 16 + ((lane16 >> 3) << 3);
            #pragma unroll
            for (int nt = 0; nt < NT8; nt++) {
                const uint32_t addr = sB + (uint32_t)((brow + nt * 8) * ROW + bcol) * 2;
                ldsm_x2(bh[nt], addr);
                ldsm_x2(bl[nt], addr + B_TILE * 2);
            }
            #pragma unroll
            for (int mt = 0; mt < 4; mt++)
                #pragma unroll
                for (int nt = 0; nt < NT8; nt++) {
                    mma_bf16(acc[mt][nt], ah[mt], bh[nt]);
                    mma_bf16(acc[mt][nt], ah[mt], bl[nt]);
                    mma_bf16(acc[mt][nt], al[mt], bh[nt]);
                }
        }
        __syncthreads();
    }

    // ---- epilogue ----
    const int erow0 = rowBase + wm * 64 + (lane >> 2);
    const int ecol0 = colBase + wn * (NT8 * 8) + (lane & 3) * 2;
    #pragma unroll
    for (int mt = 0; mt < 4; mt++) {
        #pragma unroll
        for (int nt = 0; nt < NT8; nt++) {
            const int r = erow0 + mt * 16;
            const int c = ecol0 + nt * 8;
            if (C) {
                float* Cb = C + (long long)blockIdx.z * cStride;
                *(float2*)&Cb[(long long)r * ldc + c] =
                    make_float2(acc[mt][nt][0], acc[mt][nt][1]);
                *(float2*)&Cb[(long long)(r + 8) * ldc + c] =
                    make_float2(acc[mt][nt][2], acc[mt][nt][3]);
            }
            if (Chi) {
                bf16* Hb = Chi + (long long)blockIdx.z * cStride;
                bf16* Lb = Clo + (long long)blockIdx.z * cStride;
                *(uint32_t*)&Hb[(long long)r * ldc + c] = pack_hi2(acc[mt][nt][0], acc[mt][nt][1]);
                *(uint32_t*)&Lb[(long long)r * ldc + c] = pack_lo2(acc[mt][nt][0], acc[mt][nt][1]);
                *(uint32_t*)&Hb[(long long)(r + 8) * ldc + c] = pack_hi2(acc[mt][nt][2], acc[mt][nt][3]);
                *(uint32_t*)&Lb[(long long)(r + 8) * ldc + c] = pack_lo2(acc[mt][nt][2], acc[mt][nt][3]);
            }
        }
    }
}

// ================= fp32 -> bf16 hi/lo split ===================================
__global__ void split_kernel(const float* __restrict__ in,
                             bf16* __restrict__ hi, bf16* __restrict__ lo,
                             long long n)
{
    long long i = (long long)blockIdx.x * blockDim.x + threadIdx.x;
    if (i >= n) return;
    float v = in[i];
    bf16 h = __float2bfloat16(v);
    hi[i] = h;
    lo[i] = __float2bfloat16(v - __bfloat162float(h));
}

// transpose + split: in[R][C] fp32 -> hiT/loT [C][R] bf16
__global__ void tsplit_kernel(const float* __restrict__ in,
                              bf16* __restrict__ hiT, bf16* __restrict__ loT,
                              int R, int C)
{
    __shared__ float tile[32][33];
    const int c0 = blockIdx.x * 32;
    const int r0 = blockIdx.y * 32;
    const int tx = threadIdx.x, ty = threadIdx.y;  // 32 x 8
    #pragma unroll
    for (int i = 0; i < 32; i += 8)
        tile[ty + i][tx] = in[(long long)(r0 + ty + i) * C + (c0 + tx)];
    __syncthreads();
    #pragma unroll
    for (int i = 0; i < 32; i += 8) {
        float v = tile[tx][ty + i];
        bf16 h = __float2bfloat16(v);
        long long o = (long long)(c0 + ty + i) * R + (r0 + tx);
        hiT[o] = h;
        loT[o] = __float2bfloat16(v - __bfloat162float(h));
    }
}

// ================= RoPE (reads fp32, emits bf16 hi/lo) ========================
__global__ void rope_split_kernel(const float* __restrict__ src,
                                  bf16* __restrict__ hi, bf16* __restrict__ lo,
                                  const int* __restrict__ pos,
                                  int nHeads, int rowStride)
{
    long long idx = (long long)blockIdx.x * blockDim.x + threadIdx.x;
    const long long total = (long long)S_ * nHeads * (DH_ / 2);
    if (idx >= total) return;
    int d = (int)(idx % (DH_ / 2));
    int h = (int)((idx / (DH_ / 2)) % nHeads);
    int s = (int)(idx / ((long long)(DH_ / 2) * nHeads));

    float p = (float)pos[s];
    float inv = exp2f(-((float)(2 * d) / (float)DH_) * log2f(10000.0f));
    float ang = p * inv;
    float sn, cs;
    sincosf(ang, &sn, &cs);

    const long long base = (long long)s * rowStride + h * DH_;
    float a = src[base + d];
    float b = src[base + d + 128];
    float ra = a * cs - b * sn;
    float rb = b * cs + a * sn;

    bf16 ha = __float2bfloat16(ra);
    bf16 hb = __float2bfloat16(rb);
    hi[base + d]       = ha;
    hi[base + d + 128] = hb;
    lo[base + d]       = __float2bfloat16(ra - __bfloat162float(ha));
    lo[base + d + 128] = __float2bfloat16(rb - __bfloat162float(hb));
}

// ================= causal scale + softmax (analytic mask) =====================
// Only reads scores at col <= i (others never written by the causal-skipped QK).
__global__ void softmax_kernel(float* __restrict__ attn,
                               bf16* __restrict__ phi, bf16* __restrict__ plo)
{
    const int i = blockIdx.x;
    const int h = blockIdx.y;
    const long long rowOff = ((long long)h * S_ + i) * S_;
    float* row = attn + rowOff;
    const int t = threadIdx.x;

    float vals[8];
    float mx = -INFINITY;
    #pragma unroll
    for (int j = 0; j < 8; j++) {
        int col = t + j * 256;
        float v = (col <= i) ? fmaf(row[col], SCALE_, 0.0f) : NEG_;
        vals[j] = v;
        mx = fmaxf(mx, v);
    }

    __shared__ float red[256];
    red[t] = mx;
    __syncthreads();
    #pragma unroll
    for (int s = 128; s > 0; s >>= 1) {
        if (t < s) red[t] = fmaxf(red[t], red[t + s]);
        __syncthreads();
    }
    mx = red[0];
    __syncthreads();

    float sum = 0.0f;
    #pragma unroll
    for (int j = 0; j < 8; j++) {
        vals[j] = __expf(vals[j] - mx);
        sum += vals[j];
    }
    red[t] = sum;
    __syncthreads();
    #pragma unroll
    for (int s = 128; s > 0; s >>= 1) {
        if (t < s) red[t] += red[t + s];
        __syncthreads();
    }
    sum = red[0];

    float inv = 1.0f / sum;
    #pragma unroll
    for (int j = 0; j < 8; j++) {
        int col = t + j * 256;
        float p = vals[j] * inv;
        row[col] = p;
        bf16 hp = __float2bfloat16(p);
        phi[rowOff + col] = hp;
        plo[rowOff + col] = __float2bfloat16(p - __bfloat162float(hp));
    }
}

// ================= launch ======================================================
static void* sym_addr(const void* sym)
{
    void* p = nullptr;
    cudaGetSymbolAddress(&p, sym);
    return p;
}

extern "C" void kernel_launch(void* const* d_in, const int* in_sizes, int n_in,
                              void* d_out, int out_size)
{
    const float* x    = (const float*)d_in[0];
    const int*   pos  = (const int*)  d_in[1];
    const float* wq   = (const float*)d_in[3];
    const float* wk   = (const float*)d_in[4];
    const float* wv   = (const float*)d_in[5];
    const float* wo   = (const float*)d_in[6];

    float* out  = (float*)d_out;
    float* attn = out + (long long)B_ * S_ * H_;

    float* Qf = (float*)sym_addr(g_Q);
    float* Kf = (float*)sym_addr(g_K);
    float* Vf = (float*)sym_addr(g_V);

    bf16* xhi   = (bf16*)sym_addr(g_xhi);
    bf16* xlo   = (bf16*)sym_addr(g_xlo);
    bf16* wqThi = (bf16*)sym_addr(g_wqThi);
    bf16* wqTlo = (bf16*)sym_addr(g_wqTlo);
    bf16* wkThi = (bf16*)sym_addr(g_wkThi);
    bf16* wkTlo = (bf16*)sym_addr(g_wkTlo);
    bf16* wvThi = (bf16*)sym_addr(g_wvThi);
    bf16* wvTlo = (bf16*)sym_addr(g_wvTlo);
    bf16* woThi = (bf16*)sym_addr(g_woThi);
    bf16* woTlo = (bf16*)sym_addr(g_woTlo);
    bf16* qhi   = (bf16*)sym_addr(g_qhi);
    bf16* qlo   = (bf16*)sym_addr(g_qlo);
    bf16* khi   = (bf16*)sym_addr(g_khi);
    bf16* klo   = (bf16*)sym_addr(g_klo);
    bf16* vthi  = (bf16*)sym_addr(g_vthi);
    bf16* vtlo  = (bf16*)sym_addr(g_vtlo);
    bf16* phi   = (bf16*)sym_addr(g_phi);
    bf16* plo   = (bf16*)sym_addr(g_plo);
    bf16* chi   = (bf16*)sym_addr(g_chi);
    bf16* clo   = (bf16*)sym_addr(g_clo);

    const int smem128 = 2 * (2 * 128 * 40 + 2 * 128 * 40) * 2;  // 81920
    const int smem64  = 2 * (2 * 128 * 40 + 2 *  64 * 40) * 2;  // 61440
    cudaFuncSetAttribute(mma_gemm<4>, cudaFuncAttributeMaxDynamicSharedMemorySize, smem128);
    cudaFuncSetAttribute(mma_gemm<2>, cudaFuncAttributeMaxDynamicSharedMemorySize, smem64);

    const long long SS  = (long long)S_ * S_;
    const long long nSH = (long long)S_ * H_;

    // ---- operand prep ----
    split_kernel<<<(unsigned)((nSH + 255) / 256), 256>>>(x, xhi, xlo, nSH);
    tsplit_kernel<<<dim3(H_ / 32,  H_ / 32), dim3(32, 8)>>>(wq, wqThi, wqTlo, H_, H_);
    tsplit_kernel<<<dim3(DH_ / 32, H_ / 32), dim3(32, 8)>>>(wk, wkThi, wkTlo, H_, DH_);
    tsplit_kernel<<<dim3(DH_ / 32, H_ / 32), dim3(32, 8)>>>(wv, wvThi, wvTlo, H_, DH_);
    tsplit_kernel<<<dim3(H_ / 32,  H_ / 32), dim3(32, 8)>>>(wo, woThi, woTlo, H_, H_);

    // ---- projections ----
    mma_gemm<4><<<dim3(H_ / 128, S_ / 128, 1), 256, smem128>>>(
        xhi, xlo, wqThi, wqTlo, Qf, nullptr, nullptr, H_, H_, H_, H_, 0, 0, 0, 0);
    mma_gemm<2><<<dim3(DH_ / 64, S_ / 128, 1), 256, smem64>>>(
        xhi, xlo, wkThi, wkTlo, Kf, nullptr, nullptr, H_, H_, H_, DH_, 0, 0, 0, 0);
    mma_gemm<2><<<dim3(DH_ / 64, S_ / 128, 1), 256, smem64>>>(
        xhi, xlo, wvThi, wvTlo, Vf, nullptr, nullptr, H_, H_, H_, DH_, 0, 0, 0, 0);

    // ---- RoPE -> bf16 hi/lo ----
    rope_split_kernel<<<(unsigned)(((long long)S_ * NH_ * 128 + 255) / 256), 256>>>(
        Qf, qhi, qlo, pos, NH_, H_);
    rope_split_kernel<<<(unsigned)(((long long)S_ * 128 + 255) / 256), 256>>>(
        Kf, khi, klo, pos, 1, DH_);

    // ---- V transpose + split ----
    tsplit_kernel<<<dim3(DH_ / 32, S_ / 32), dim3(32, 8)>>>(Vf, vthi, vtlo, S_, DH_);

    // ---- scores: attn_h = Q_h @ K^T, causal tile skip ----
    mma_gemm<4><<<dim3(S_ / 128, S_ / 128, NH_), 256, smem128>>>(
        qhi, qlo, khi, klo, attn, nullptr, nullptr, DH_, H_, DH_, S_, DH_, 0, SS, 1);

    // ---- softmax (analytic causal mask) ----
    softmax_kernel<<<dim3(S_, NH_), 256>>>(attn, phi, plo);

    // ---- ctx_h = P_h @ V, causal K-limit, fused bf16 split epilogue ----
    mma_gemm<4><<<dim3(DH_ / 128, S_ / 128, NH_), 256, smem128>>>(
        phi, plo, vthi, vtlo, nullptr, chi, clo, S_, S_, S_, H_, SS, 0, DH_, 2);

    // ---- out = ctx @ w_o ----
    mma_gemm<4><<<dim3(H_ / 128, S_ / 128, 1), 256, smem128>>>(
        chi, clo, woThi, woTlo, out, nullptr, nullptr, H_, H_, H_, H_, 0, 0, 0, 0);
}

// round 6
// speedup vs baseline: 4.4175x; 1.0979x over previous
#include <cuda_runtime.h>
#include <cuda_bf16.h>
#include <cstdint>
#include <math.h>

// Problem constants
#define B_  1
#define S_  2048
#define H_  2048
#define NH_ 8
#define DH_ 256
#define SCALE_ 0.0625f   // 256^-0.5
#define NEG_  -1000000000.0f

typedef __nv_bfloat16 bf16;

// ================= helpers =====================================================
__device__ __forceinline__ uint32_t smem_to_u32(const void* smem_ptr) {
    uint32_t addr;
    asm("{ .reg .u64 tmp; cvta.to.shared.u64 tmp, %1; cvt.u32.u64 %0, tmp; }"
        : "=r"(addr) : "l"(smem_ptr));
    return addr;
}

__device__ __forceinline__ void cp_async16(uint32_t dst, const void* src) {
    asm volatile("cp.async.cg.shared.global [%0], [%1], 16;\n"
                 :: "r"(dst), "l"(src) : "memory");
}

__device__ __forceinline__ void ldsm_x4(uint32_t r[4], uint32_t addr) {
    asm volatile("ldmatrix.sync.aligned.m8n8.x4.shared.b16 {%0,%1,%2,%3}, [%4];"
                 : "=r"(r[0]), "=r"(r[1]), "=r"(r[2]), "=r"(r[3]) : "r"(addr));
}

__device__ __forceinline__ void ldsm_x2(uint32_t r[2], uint32_t addr) {
    asm volatile("ldmatrix.sync.aligned.m8n8.x2.shared.b16 {%0,%1}, [%2];"
                 : "=r"(r[0]), "=r"(r[1]) : "r"(addr));
}

__device__ __forceinline__ void mma_bf16(float acc[4], const uint32_t a[4], const uint32_t b[2]) {
    asm volatile(
        "mma.sync.aligned.m16n8k16.row.col.f32.bf16.bf16.f32 "
        "{%0,%1,%2,%3}, {%4,%5,%6,%7}, {%8,%9}, {%0,%1,%2,%3};"
        : "+f"(acc[0]), "+f"(acc[1]), "+f"(acc[2]), "+f"(acc[3])
        : "r"(a[0]), "r"(a[1]), "r"(a[2]), "r"(a[3]), "r"(b[0]), "r"(b[1]));
}

__device__ __forceinline__ uint32_t pack_hi2(float v0, float v1) {
    bf16 h0 = __float2bfloat16(v0);
    bf16 h1 = __float2bfloat16(v1);
    return (uint32_t)__bfloat16_as_ushort(h0) | ((uint32_t)__bfloat16_as_ushort(h1) << 16);
}
__device__ __forceinline__ uint32_t pack_lo2(float v0, float v1) {
    bf16 h0 = __float2bfloat16(v0);
    bf16 h1 = __float2bfloat16(v1);
    bf16 l0 = __float2bfloat16(v0 - __bfloat162float(h0));
    bf16 l1 = __float2bfloat16(v1 - __bfloat162float(h1));
    return (uint32_t)__bfloat16_as_ushort(l0) | ((uint32_t)__bfloat16_as_ushort(l1) << 16);
}

// ================= scratch (device globals; no allocation) ====================
__device__ __align__(128) float g_Q  [S_ * H_];
__device__ __align__(128) float g_K  [S_ * DH_];
__device__ __align__(128) float g_V  [S_ * DH_];

__device__ __align__(128) bf16 g_xhi [S_ * H_];
__device__ __align__(128) bf16 g_xlo [S_ * H_];
__device__ __align__(128) bf16 g_wqThi[H_ * H_];
__device__ __align__(128) bf16 g_wqTlo[H_ * H_];
__device__ __align__(128) bf16 g_wkThi[DH_ * H_];
__device__ __align__(128) bf16 g_wkTlo[DH_ * H_];
__device__ __align__(128) bf16 g_wvThi[DH_ * H_];
__device__ __align__(128) bf16 g_wvTlo[DH_ * H_];
__device__ __align__(128) bf16 g_woThi[H_ * H_];
__device__ __align__(128) bf16 g_woTlo[H_ * H_];
__device__ __align__(128) bf16 g_qhi [S_ * H_];
__device__ __align__(128) bf16 g_qlo [S_ * H_];
__device__ __align__(128) bf16 g_khi [S_ * DH_];
__device__ __align__(128) bf16 g_klo [S_ * DH_];
__device__ __align__(128) bf16 g_vthi[DH_ * S_];
__device__ __align__(128) bf16 g_vtlo[DH_ * S_];
__device__ __align__(128) bf16 g_phi [(long long)NH_ * S_ * S_];
__device__ __align__(128) bf16 g_plo [(long long)NH_ * S_ * S_];
__device__ __align__(128) bf16 g_chi [S_ * H_];
__device__ __align__(128) bf16 g_clo [S_ * H_];

// ================= split-bf16 mma.sync GEMM ===================================
// C = (Ahi+Alo) @ (Bhi+Blo)^T  via 3 HMMA passes (hh + hl + lh), fp32 accum.
// A: M x K (K-major, lda); B: N x K (K-major, ldb).
// Output: fp32 C and/or bf16 hi/lo Chi/Clo (non-null selects), both ldc.
// CTA: 128 x (NT8*32), 256 threads = 8 warps in 2(m) x 4(n), warp tile 64 x (NT8*8).
// mode bit0: causal tile skip (skip if colBase > rowBase+127)
// mode bit1: causal K limit   (K_eff = min(K, rowBase+128))
template<int NT8>
__global__ __launch_bounds__(256, 2)
void mma_gemm(const bf16* __restrict__ Ahi, const bf16* __restrict__ Alo,
              const bf16* __restrict__ Bhi, const bf16* __restrict__ Blo,
              float* __restrict__ C,
              bf16* __restrict__ Chi, bf16* __restrict__ Clo,
              int K, int lda, int ldb, int ldc,
              long long aStride, long long bStride, long long cStride,
              int mode)
{
    constexpr int TN     = NT8 * 32;
    constexpr int ROW    = 40;                       // padded bf16 per smem row (80B)
    constexpr int A_TILE = 128 * ROW;
    constexpr int B_TILE = TN * ROW;
    constexpr int STAGE  = 2 * A_TILE + 2 * B_TILE;

    const int rowBase = blockIdx.y * 128;
    const int colBase = blockIdx.x * TN;

    if ((mode & 1) && colBase > rowBase + 127) return;

    int Keff = K;
    if (mode & 2) Keff = min(K, rowBase + 128);

    extern __shared__ bf16 smem[];
    const uint32_t sbase = smem_to_u32(smem);

    const int tid  = threadIdx.x;
    const int wid  = tid >> 5;
    const int lane = tid & 31;
    const int wm   = wid & 1;              // m warp 0..1 -> rows 64*wm
    const int wn   = wid >> 1;             // n warp 0..3 -> cols (NT8*8)*wn

    Ahi += (long long)blockIdx.z * aStride;
    Alo += (long long)blockIdx.z * aStride;
    Bhi += (long long)blockIdx.z * bStride;
    Blo += (long long)blockIdx.z * bStride;

    float acc[4][NT8][4] = {};

    const int nStages = Keff >> 5;

    // loader: 256 threads, A: 128 rows x 4 chunks -> 2 rows/thread
    const int lrow = tid >> 2;          // 0..63
    const int lch  = tid & 3;

    auto issue = [&](int s) {
        const int buf = s & 1;
        const uint32_t sb = sbase + (uint32_t)buf * STAGE * 2;
        const int kt = s << 5;
        #pragma unroll
        for (int half = 0; half < 2; half++) {
            const int r = lrow + half * 64;
            const long long g = (long long)(rowBase + r) * lda + kt + lch * 8;
            const uint32_t d = sb + (uint32_t)(r * ROW + lch * 8) * 2;
            cp_async16(d,              Ahi + g);
            cp_async16(d + A_TILE * 2, Alo + g);
        }
        if (TN == 128) {
            #pragma unroll
            for (int half = 0; half < 2; half++) {
                const int r = lrow + half * 64;
                const long long g = (long long)(colBase + r) * ldb + kt + lch * 8;
                const uint32_t d = sb + (uint32_t)(2 * A_TILE + r * ROW + lch * 8) * 2;
                cp_async16(d,              Bhi + g);
                cp_async16(d + B_TILE * 2, Blo + g);
            }
        } else {
            const long long g = (long long)(colBase + lrow) * ldb + kt + lch * 8;
            const uint32_t d = sb + (uint32_t)(2 * A_TILE + lrow * ROW + lch * 8) * 2;
            cp_async16(d,              Bhi + g);
            cp_async16(d + B_TILE * 2, Blo + g);
        }
        asm volatile("cp.async.commit_group;\n" ::: "memory");
    };

    issue(0);

    for (int s = 0; s < nStages; s++) {
        if (s + 1 < nStages) {
            issue(s + 1);
            asm volatile("cp.async.wait_group 1;\n" ::: "memory");
        } else {
            asm volatile("cp.async.wait_group 0;\n" ::: "memory");
        }
        __syncthreads();

        const uint32_t sb = sbase + (uint32_t)(s & 1) * STAGE * 2;
        const uint32_t sA = sb;
        const uint32_t sB = sb + 2 * A_TILE * 2;

        #pragma unroll
        for (int kk = 0; kk < 2; kk++) {
            // ---- B fragments first (16 regs live across mt loop) ----
            uint32_t bh[NT8][2], bl[NT8][2];
            const int lane16 = lane & 15;
            const int brow = wn * (NT8 * 8) + (lane16 & 7);
            const int bcol = kk * 16 + ((lane16 >> 3) << 3);
            #pragma unroll
            for (int nt = 0; nt < NT8; nt++) {
                const uint32_t addr = sB + (uint32_t)((brow + nt * 8) * ROW + bcol) * 2;
                ldsm_x2(bh[nt], addr);
                ldsm_x2(bl[nt], addr + B_TILE * 2);
            }
            // ---- per-mt A fragments (only 8 regs live at a time) ----
            const int arow = wm * 64 + (lane & 15);
            const int acol = kk * 16 + ((lane >> 4) << 3);
            #pragma unroll
            for (int mt = 0; mt < 4; mt++) {
                uint32_t ah[4], al[4];
                const uint32_t addr = sA + (uint32_t)((arow + mt * 16) * ROW + acol) * 2;
                ldsm_x4(ah, addr);
                ldsm_x4(al, addr + A_TILE * 2);
                #pragma unroll
                for (int nt = 0; nt < NT8; nt++) {
                    mma_bf16(acc[mt][nt], ah, bh[nt]);
                    mma_bf16(acc[mt][nt], ah, bl[nt]);
                    mma_bf16(acc[mt][nt], al, bh[nt]);
                }
            }
        }
        __syncthreads();
    }

    // ---- epilogue ----
    const int erow0 = rowBase + wm * 64 + (lane >> 2);
    const int ecol0 = colBase + wn * (NT8 * 8) + (lane & 3) * 2;
    #pragma unroll
    for (int mt = 0; mt < 4; mt++) {
        #pragma unroll
        for (int nt = 0; nt < NT8; nt++) {
            const int r = erow0 + mt * 16;
            const int c = ecol0 + nt * 8;
            if (C) {
                float* Cb = C + (long long)blockIdx.z * cStride;
                *(float2*)&Cb[(long long)r * ldc + c] =
                    make_float2(acc[mt][nt][0], acc[mt][nt][1]);
                *(float2*)&Cb[(long long)(r + 8) * ldc + c] =
                    make_float2(acc[mt][nt][2], acc[mt][nt][3]);
            }
            if (Chi) {
                bf16* Hb = Chi + (long long)blockIdx.z * cStride;
                bf16* Lb = Clo + (long long)blockIdx.z * cStride;
                *(uint32_t*)&Hb[(long long)r * ldc + c] = pack_hi2(acc[mt][nt][0], acc[mt][nt][1]);
                *(uint32_t*)&Lb[(long long)r * ldc + c] = pack_lo2(acc[mt][nt][0], acc[mt][nt][1]);
                *(uint32_t*)&Hb[(long long)(r + 8) * ldc + c] = pack_hi2(acc[mt][nt][2], acc[mt][nt][3]);
                *(uint32_t*)&Lb[(long long)(r + 8) * ldc + c] = pack_lo2(acc[mt][nt][2], acc[mt][nt][3]);
            }
        }
    }
}

// ================= fp32 -> bf16 hi/lo split ===================================
__global__ void split_kernel(const float* __restrict__ in,
                             bf16* __restrict__ hi, bf16* __restrict__ lo,
                             long long n)
{
    long long i = (long long)blockIdx.x * blockDim.x + threadIdx.x;
    if (i >= n) return;
    float v = in[i];
    bf16 h = __float2bfloat16(v);
    hi[i] = h;
    lo[i] = __float2bfloat16(v - __bfloat162float(h));
}

// transpose + split: in[R][C] fp32 -> hiT/loT [C][R] bf16
__global__ void tsplit_kernel(const float* __restrict__ in,
                              bf16* __restrict__ hiT, bf16* __restrict__ loT,
                              int R, int C)
{
    __shared__ float tile[32][33];
    const int c0 = blockIdx.x * 32;
    const int r0 = blockIdx.y * 32;
    const int tx = threadIdx.x, ty = threadIdx.y;  // 32 x 8
    #pragma unroll
    for (int i = 0; i < 32; i += 8)
        tile[ty + i][tx] = in[(long long)(r0 + ty + i) * C + (c0 + tx)];
    __syncthreads();
    #pragma unroll
    for (int i = 0; i < 32; i += 8) {
        float v = tile[tx][ty + i];
        bf16 h = __float2bfloat16(v);
        long long o = (long long)(c0 + ty + i) * R + (r0 + tx);
        hiT[o] = h;
        loT[o] = __float2bfloat16(v - __bfloat162float(h));
    }
}

// ================= RoPE (reads fp32, emits bf16 hi/lo) ========================
__global__ void rope_split_kernel(const float* __restrict__ src,
                                  bf16* __restrict__ hi, bf16* __restrict__ lo,
                                  const int* __restrict__ pos,
                                  int nHeads, int rowStride)
{
    long long idx = (long long)blockIdx.x * blockDim.x + threadIdx.x;
    const long long total = (long long)S_ * nHeads * (DH_ / 2);
    if (idx >= total) return;
    int d = (int)(idx % (DH_ / 2));
    int h = (int)((idx / (DH_ / 2)) % nHeads);
    int s = (int)(idx / ((long long)(DH_ / 2) * nHeads));

    float p = (float)pos[s];
    float inv = exp2f(-((float)(2 * d) / (float)DH_) * log2f(10000.0f));
    float ang = p * inv;
    float sn, cs;
    sincosf(ang, &sn, &cs);

    const long long base = (long long)s * rowStride + h * DH_;
    float a = src[base + d];
    float b = src[base + d + 128];
    float ra = a * cs - b * sn;
    float rb = b * cs + a * sn;

    bf16 ha = __float2bfloat16(ra);
    bf16 hb = __float2bfloat16(rb);
    hi[base + d]       = ha;
    hi[base + d + 128] = hb;
    lo[base + d]       = __float2bfloat16(ra - __bfloat162float(ha));
    lo[base + d + 128] = __float2bfloat16(rb - __bfloat162float(hb));
}

// ================= causal scale + softmax (analytic mask) =====================
__global__ void softmax_kernel(float* __restrict__ attn,
                               bf16* __restrict__ phi, bf16* __restrict__ plo)
{
    const int i = blockIdx.x;
    const int h = blockIdx.y;
    const long long rowOff = ((long long)h * S_ + i) * S_;
    float* row = attn + rowOff;
    const int t = threadIdx.x;

    // AV only reads cols < kLimit (causal K-limit granularity = 128)
    const int kLimit = ((i >> 7) + 1) << 7;

    float vals[8];
    float mx = -INFINITY;
    #pragma unroll
    for (int j = 0; j < 8; j++) {
        int col = t + j * 256;
        float v = (col <= i) ? fmaf(row[col], SCALE_, 0.0f) : NEG_;
        vals[j] = v;
        mx = fmaxf(mx, v);
    }

    __shared__ float red[256];
    red[t] = mx;
    __syncthreads();
    #pragma unroll
    for (int s = 128; s > 0; s >>= 1) {
        if (t < s) red[t] = fmaxf(red[t], red[t + s]);
        __syncthreads();
    }
    mx = red[0];
    __syncthreads();

    float sum = 0.0f;
    #pragma unroll
    for (int j = 0; j < 8; j++) {
        vals[j] = __expf(vals[j] - mx);
        sum += vals[j];
    }
    red[t] = sum;
    __syncthreads();
    #pragma unroll
    for (int s = 128; s > 0; s >>= 1) {
        if (t < s) red[t] += red[t + s];
        __syncthreads();
    }
    sum = red[0];

    float inv = 1.0f / sum;
    #pragma unroll
    for (int j = 0; j < 8; j++) {
        int col = t + j * 256;
        float p = vals[j] * inv;
        row[col] = p;                       // fp32 attn output: full row (overwrite poison)
        if (col < kLimit) {                 // bf16 P only where AV will read
            bf16 hp = __float2bfloat16(p);
            phi[rowOff + col] = hp;
            plo[rowOff + col] = __float2bfloat16(p - __bfloat162float(hp));
        }
    }
}

// ================= launch ======================================================
static void* sym_addr(const void* sym)
{
    void* p = nullptr;
    cudaGetSymbolAddress(&p, sym);
    return p;
}

extern "C" void kernel_launch(void* const* d_in, const int* in_sizes, int n_in,
                              void* d_out, int out_size)
{
    const float* x    = (const float*)d_in[0];
    const int*   pos  = (const int*)  d_in[1];
    const float* wq   = (const float*)d_in[3];
    const float* wk   = (const float*)d_in[4];
    const float* wv   = (const float*)d_in[5];
    const float* wo   = (const float*)d_in[6];

    float* out  = (float*)d_out;
    float* attn = out + (long long)B_ * S_ * H_;

    float* Qf = (float*)sym_addr(g_Q);
    float* Kf = (float*)sym_addr(g_K);
    float* Vf = (float*)sym_addr(g_V);

    bf16* xhi   = (bf16*)sym_addr(g_xhi);
    bf16* xlo   = (bf16*)sym_addr(g_xlo);
    bf16* wqThi = (bf16*)sym_addr(g_wqThi);
    bf16* wqTlo = (bf16*)sym_addr(g_wqTlo);
    bf16* wkThi = (bf16*)sym_addr(g_wkThi);
    bf16* wkTlo = (bf16*)sym_addr(g_wkTlo);
    bf16* wvThi = (bf16*)sym_addr(g_wvThi);
    bf16* wvTlo = (bf16*)sym_addr(g_wvTlo);
    bf16* woThi = (bf16*)sym_addr(g_woThi);
    bf16* woTlo = (bf16*)sym_addr(g_woTlo);
    bf16* qhi   = (bf16*)sym_addr(g_qhi);
    bf16* qlo   = (bf16*)sym_addr(g_qlo);
    bf16* khi   = (bf16*)sym_addr(g_khi);
    bf16* klo   = (bf16*)sym_addr(g_klo);
    bf16* vthi  = (bf16*)sym_addr(g_vthi);
    bf16* vtlo  = (bf16*)sym_addr(g_vtlo);
    bf16* phi   = (bf16*)sym_addr(g_phi);
    bf16* plo   = (bf16*)sym_addr(g_plo);
    bf16* chi   = (bf16*)sym_addr(g_chi);
    bf16* clo   = (bf16*)sym_addr(g_clo);

    const int smem128 = 2 * (2 * 128 * 40 + 2 * 128 * 40) * 2;  // 81920
    const int smem64  = 2 * (2 * 128 * 40 + 2 *  64 * 40) * 2;  // 61440
    cudaFuncSetAttribute(mma_gemm<4>, cudaFuncAttributeMaxDynamicSharedMemorySize, smem128);
    cudaFuncSetAttribute(mma_gemm<2>, cudaFuncAttributeMaxDynamicSharedMemorySize, smem64);

    const long long SS  = (long long)S_ * S_;
    const long long nSH = (long long)S_ * H_;

    // ---- operand prep ----
    split_kernel<<<(unsigned)((nSH + 255) / 256), 256>>>(x, xhi, xlo, nSH);
    tsplit_kernel<<<dim3(H_ / 32,  H_ / 32), dim3(32, 8)>>>(wq, wqThi, wqTlo, H_, H_);
    tsplit_kernel<<<dim3(DH_ / 32, H_ / 32), dim3(32, 8)>>>(wk, wkThi, wkTlo, H_, DH_);
    tsplit_kernel<<<dim3(DH_ / 32, H_ / 32), dim3(32, 8)>>>(wv, wvThi, wvTlo, H_, DH_);
    tsplit_kernel<<<dim3(H_ / 32,  H_ / 32), dim3(32, 8)>>>(wo, woThi, woTlo, H_, H_);

    // ---- projections: Q alone; K and V fused via z-batch (pointer-diff strides) ----
    mma_gemm<4><<<dim3(H_ / 128, S_ / 128, 1), 256, smem128>>>(
        xhi, xlo, wqThi, wqTlo, Qf, nullptr, nullptr, H_, H_, H_, H_, 0, 0, 0, 0);
    {
        const long long bS = (long long)(wvThi - wkThi);   // same offset applies to lo arrays
        const long long cS = (long long)(Vf - Kf);
        mma_gemm<2><<<dim3(DH_ / 64, S_ / 128, 2), 256, smem64>>>(
            xhi, xlo, wkThi, wkTlo, Kf, nullptr, nullptr, H_, H_, H_, DH_, 0, bS, cS, 0);
    }

    // ---- RoPE -> bf16 hi/lo ----
    rope_split_kernel<<<(unsigned)(((long long)S_ * NH_ * 128 + 255) / 256), 256>>>(
        Qf, qhi, qlo, pos, NH_, H_);
    rope_split_kernel<<<(unsigned)(((long long)S_ * 128 + 255) / 256), 256>>>(
        Kf, khi, klo, pos, 1, DH_);

    // ---- V transpose + split ----
    tsplit_kernel<<<dim3(DH_ / 32, S_ / 32), dim3(32, 8)>>>(Vf, vthi, vtlo, S_, DH_);

    // ---- scores: attn_h = Q_h @ K^T, causal tile skip ----
    mma_gemm<4><<<dim3(S_ / 128, S_ / 128, NH_), 256, smem128>>>(
        qhi, qlo, khi, klo, attn, nullptr, nullptr, DH_, H_, DH_, S_, DH_, 0, SS, 1);

    // ---- softmax (analytic causal mask) ----
    softmax_kernel<<<dim3(S_, NH_), 256>>>(attn, phi, plo);

    // ---- ctx_h = P_h @ V, causal K-limit, fused bf16 split epilogue ----
    mma_gemm<4><<<dim3(DH_ / 128, S_ / 128, NH_), 256, smem128>>>(
        phi, plo, vthi, vtlo, nullptr, chi, clo, S_, S_, S_, H_, SS, 0, DH_, 2);

    // ---- out = ctx @ w_o ----
    mma_gemm<4><<<dim3(H_ / 128, S_ / 128, 1), 256, smem128>>>(
        chi, clo, woThi, woTlo, out, nullptr, nullptr, H_, H_, H_, H_, 0, 0, 0, 0);
}